// round 10
// baseline (speedup 1.0000x reference)
#include <cuda_runtime.h>

// HierarchyInvertClassifier: out[b,k,h,w] = bias[k] + sum_{c in group k} w[c]*in[b,c,h,w]
// B=8, C=64, H=W=512, K=12. Groups are contiguous channel ranges (static).
//
// HBM-bound pure stream: 512 MiB read + 96 MiB write, zero reuse.
// R10: ILP=2 — each thread processes TWO float4 positions (128 vecs apart),
// giving two independent LDG streams per inner iteration (doubles intrinsic
// per-warp MLP, the commodity the R2-R8 sweep showed matters most).
// Per-group accumulate+store, streaming hints, 64-reg budget (128,8).
// Fallback if this regresses: R4 config (128,10, ILP=1) at 96.4us.

#define HW    (512 * 512)
#define HW4   (HW / 4)        // 65536 float4 per plane
#define CCH   64
#define KOUT  12
#define TPB   128             // threads per block
#define VPB   (2 * TPB)       // vec positions per block = 256
#define BLKPI (HW4 / VPB)     // blocks per image = 256

__constant__ int kGroupStart[KOUT + 1] = {0, 1, 4, 14, 20, 28, 38, 46, 52, 57, 59, 62, 64};

__global__ __launch_bounds__(TPB, 8)
void hier_invert_kernel(const float4* __restrict__ in4,
                        const float*  __restrict__ w,
                        const float*  __restrict__ bias,
                        float4* __restrict__ out4)
{
    __shared__ float sw[CCH];
    __shared__ float sb[KOUT];
    int t = threadIdx.x;
    if (t < CCH)  sw[t] = w[t];
    if (t < KOUT) sb[t] = bias[t];
    __syncthreads();

    int bimg = blockIdx.x >> 8;               // image index (0..7)
    int blk  = blockIdx.x & (BLKPI - 1);      // block within image
    int p0   = blk * VPB + t;                 // first vec position
    // second position is p0 + TPB (both warp-coalesced)

    const float4* ip = in4 + ((long)bimg * CCH) * HW4 + p0;
    float4*       op = out4 + ((long)bimg * KOUT) * HW4 + p0;

    #pragma unroll
    for (int k = 0; k < KOUT; k++) {
        const int c0 = kGroupStart[k];
        const int c1 = kGroupStart[k + 1];
        float bk = sb[k];
        float4 a0 = make_float4(bk, bk, bk, bk);
        float4 a1 = a0;
        #pragma unroll
        for (int c = c0; c < c1; c++) {
            const float4* p = ip + (long)c * HW4;
            float4 v0 = __ldcs(p);
            float4 v1 = __ldcs(p + TPB);
            float  wc = sw[c];
            a0.x = fmaf(wc, v0.x, a0.x);
            a0.y = fmaf(wc, v0.y, a0.y);
            a0.z = fmaf(wc, v0.z, a0.z);
            a0.w = fmaf(wc, v0.w, a0.w);
            a1.x = fmaf(wc, v1.x, a1.x);
            a1.y = fmaf(wc, v1.y, a1.y);
            a1.z = fmaf(wc, v1.z, a1.z);
            a1.w = fmaf(wc, v1.w, a1.w);
        }
        float4* q = op + (long)k * HW4;
        __stcs(q, a0);
        __stcs(q + TPB, a1);
    }
}

extern "C" void kernel_launch(void* const* d_in, const int* in_sizes, int n_in,
                              void* d_out, int out_size)
{
    const float* pred_lr = (const float*)d_in[0];   // [8,64,512,512]
    const float* weights = (const float*)d_in[1];   // [64]
    const float* biases  = (const float*)d_in[2];   // [12]
    float* out = (float*)d_out;                     // [8,12,512,512]

    int blocks = 8 * BLKPI;                         // 2048

    hier_invert_kernel<<<blocks, TPB>>>(
        (const float4*)pred_lr, weights, biases, (float4*)out);
}

// round 11
// speedup vs baseline: 1.0103x; 1.0103x over previous
#include <cuda_runtime.h>

// HierarchyInvertClassifier: out[b,k,h,w] = bias[k] + sum_{c in group k} w[c]*in[b,c,h,w]
// B=8, C=64, H=W=512, K=12. Groups are contiguous channel ranges (static).
//
// HBM-bound pure stream: 512 MiB read + 96 MiB write, zero reuse.
// R11 = R10's ILP=2 (two independent LDG streams/thread -> DRAM 82.9%)
//       + R4's fine granularity (4096 blocks -> small drain-tail quantum).
// 64-thread blocks, launch_bounds(64,16) = 64-reg budget (no cap-induced
// batch shrink), per-group accumulate+store, streaming hints.
// Sweep so far: R4 (ILP=1,128t,4096blk)=96.4us; R10 (ILP=2,128t,2048blk)=97.2us
// wall but 93.2us ncu (tail-limited).

#define HW    (512 * 512)
#define HW4   (HW / 4)        // 65536 float4 per plane
#define CCH   64
#define KOUT  12
#define TPB   64              // threads per block
#define VPB   (2 * TPB)       // vec positions per block = 128
#define BLKPI (HW4 / VPB)     // blocks per image = 512

__constant__ int kGroupStart[KOUT + 1] = {0, 1, 4, 14, 20, 28, 38, 46, 52, 57, 59, 62, 64};

__global__ __launch_bounds__(TPB, 16)
void hier_invert_kernel(const float4* __restrict__ in4,
                        const float*  __restrict__ w,
                        const float*  __restrict__ bias,
                        float4* __restrict__ out4)
{
    __shared__ float sw[CCH];
    __shared__ float sb[KOUT];
    int t = threadIdx.x;
    sw[t] = w[t];
    if (t < KOUT) sb[t] = bias[t];
    __syncthreads();

    int bimg = blockIdx.x >> 9;               // image index (0..7), 512 blocks/image
    int blk  = blockIdx.x & (BLKPI - 1);      // block within image
    int p0   = blk * VPB + t;                 // first vec position
    // second position is p0 + TPB (both warp-coalesced)

    const float4* ip = in4 + ((long)bimg * CCH) * HW4 + p0;
    float4*       op = out4 + ((long)bimg * KOUT) * HW4 + p0;

    #pragma unroll
    for (int k = 0; k < KOUT; k++) {
        const int c0 = kGroupStart[k];
        const int c1 = kGroupStart[k + 1];
        float bk = sb[k];
        float4 a0 = make_float4(bk, bk, bk, bk);
        float4 a1 = a0;
        #pragma unroll
        for (int c = c0; c < c1; c++) {
            const float4* p = ip + (long)c * HW4;
            float4 v0 = __ldcs(p);
            float4 v1 = __ldcs(p + TPB);
            float  wc = sw[c];
            a0.x = fmaf(wc, v0.x, a0.x);
            a0.y = fmaf(wc, v0.y, a0.y);
            a0.z = fmaf(wc, v0.z, a0.z);
            a0.w = fmaf(wc, v0.w, a0.w);
            a1.x = fmaf(wc, v1.x, a1.x);
            a1.y = fmaf(wc, v1.y, a1.y);
            a1.z = fmaf(wc, v1.z, a1.z);
            a1.w = fmaf(wc, v1.w, a1.w);
        }
        float4* q = op + (long)k * HW4;
        __stcs(q, a0);
        __stcs(q + TPB, a1);
    }
}

extern "C" void kernel_launch(void* const* d_in, const int* in_sizes, int n_in,
                              void* d_out, int out_size)
{
    const float* pred_lr = (const float*)d_in[0];   // [8,64,512,512]
    const float* weights = (const float*)d_in[1];   // [64]
    const float* biases  = (const float*)d_in[2];   // [12]
    float* out = (float*)d_out;                     // [8,12,512,512]

    int blocks = 8 * BLKPI;                         // 4096

    hier_invert_kernel<<<blocks, TPB>>>(
        (const float4*)pred_lr, weights, biases, (float4*)out);
}